// round 1
// baseline (speedup 1.0000x reference)
#include <cuda_runtime.h>

// Problem constants (fixed shapes from reference)
#define B_   16
#define T_   256
#define D_   512
#define L_   51
#define LL   (L_ * L_)        // 2601
#define M_   (B_ * T_)        // 4096
#define NS   L_               // 51
#define NTW  LL               // 2601
#define NTMU (LL * 2)         // 5202
#define NTVAR (LL * 4)        // 10404
#define LOG2PI_F 1.8378770664093453f

// ---------------------------------------------------------------------------
// Scratch (static __device__ globals; no runtime allocation allowed)
// ---------------------------------------------------------------------------
__device__ float g_sw  [M_ * NS];     // s_w  projections (raw + bias)
__device__ float g_smu [M_ * NS];     // s_mu
__device__ float g_svar[M_ * NS];     // s_var raw (exp(clip) applied in scan)
__device__ float g_tw  [M_ * NTW];    // t_w
__device__ float g_tmu [M_ * NTMU];   // t_mu  (.., 2)
__device__ float g_traw[M_ * NTVAR];  // t_raw (.., 2, 2)

// ---------------------------------------------------------------------------
// fp32 SGEMM: C[M_ x N] = A[M_ x 512] @ W[512 x N] + bias[N]
// BM=128, BN=128, BK=8, 256 threads, 8x8 per-thread microtile.
// M=4096 (divisible by 128), K=512 (divisible by 8); N guarded.
// ---------------------------------------------------------------------------
__global__ __launch_bounds__(256) void sgemm_k(
    const float* __restrict__ A, const float* __restrict__ W,
    const float* __restrict__ bias, float* __restrict__ C, int N)
{
    __shared__ float As[8][128];
    __shared__ float Bs[8][128];

    const int tid = threadIdx.x;
    const int m0 = blockIdx.y * 128;
    const int n0 = blockIdx.x * 128;
    const int ty = tid >> 4;        // 0..15
    const int tx = tid & 15;        // 0..15

    float acc[8][8];
#pragma unroll
    for (int r = 0; r < 8; ++r)
#pragma unroll
        for (int c = 0; c < 8; ++c) acc[r][c] = 0.f;

    const int arow = tid >> 1;        // 0..127
    const int acol = (tid & 1) * 4;   // 0 or 4
    const int brow = tid >> 5;        // 0..7
    const int bcol = (tid & 31) * 4;  // 0..124

    const float* Ap = A + (size_t)(m0 + arow) * D_ + acol;

    for (int kt = 0; kt < D_; kt += 8) {
        // A tile (float4, always aligned: K stride 512, acol multiple of 4)
        float4 av = *reinterpret_cast<const float4*>(Ap + kt);
        As[acol + 0][arow] = av.x;
        As[acol + 1][arow] = av.y;
        As[acol + 2][arow] = av.z;
        As[acol + 3][arow] = av.w;

        // B tile (scalar guarded loads: N may be odd / not multiple of 4)
        const float* Wp = W + (size_t)(kt + brow) * N + n0 + bcol;
#pragma unroll
        for (int u = 0; u < 4; ++u) {
            int gn = n0 + bcol + u;
            Bs[brow][bcol + u] = (gn < N) ? Wp[u] : 0.f;
        }
        __syncthreads();

#pragma unroll
        for (int k = 0; k < 8; ++k) {
            float ar[8], br[8];
#pragma unroll
            for (int r = 0; r < 8; ++r) ar[r] = As[k][ty * 8 + r];
#pragma unroll
            for (int c = 0; c < 8; ++c) br[c] = Bs[k][tx * 8 + c];
#pragma unroll
            for (int r = 0; r < 8; ++r)
#pragma unroll
                for (int c = 0; c < 8; ++c)
                    acc[r][c] = fmaf(ar[r], br[c], acc[r][c]);
        }
        __syncthreads();
    }

#pragma unroll
    for (int r = 0; r < 8; ++r) {
        const int gm = m0 + ty * 8 + r;
#pragma unroll
        for (int c = 0; c < 8; ++c) {
            const int gn = n0 + tx * 8 + c;
            if (gn < N) C[(size_t)gm * N + gn] = acc[r][c] + bias[gn];
        }
    }
}

// ---------------------------------------------------------------------------
// Scan: one thread per (b, i, j) chain; sequential over t.
// Transition prep (exp/tanh/2x2 inverse/zeta1) fused in-place from raw
// projections (avoids a 512MB intermediate round-trip).
// ---------------------------------------------------------------------------
struct Pre { float a, bo, dd, e0, e1, z1; };

__device__ __forceinline__ Pre load_pre(int m, int ij)
{
    const float4 rv = *reinterpret_cast<const float4*>(
        &g_traw[(size_t)m * NTVAR + (size_t)ij * 4]);
    const float2 mv = *reinterpret_cast<const float2*>(
        &g_tmu[(size_t)m * NTMU + (size_t)ij * 2]);

    const float c0 = fminf(fmaxf(rv.x, -1.f), 1.f);   // t_raw[...,0,0]
    const float c1 = fminf(fmaxf(rv.w, -1.f), 1.f);   // t_raw[...,1,1]
    const float d0 = __expf(c0);
    const float d1 = __expf(c1);
    const float s  = rv.y + rv.z;                     // r01 + r10
    // tanh(0.5*s) = 1 - 2/(exp(s)+1)   (saturates correctly at +/-1)
    const float th  = 1.f - 2.f * __fdividef(1.f, __expf(s) + 1.f);
    // sqrt(d0*d1) = exp(0.5*(c0+c1))
    const float off = 0.9f * th * __expf(0.5f * (c0 + c1));

    const float det  = d0 * d1 - off * off;           // >= 0.19*d0*d1 > 0
    const float rdet = __fdividef(1.f, det);
    Pre p;
    p.a  = d1 * rdet;
    p.bo = -off * rdet;
    p.dd = d0 * rdet;
    p.e0 = p.a  * mv.x + p.bo * mv.y;
    p.e1 = p.bo * mv.x + p.dd * mv.y;
    const float quad = p.e0 * p.e0 * d0 + 2.f * p.e0 * p.e1 * off + p.e1 * p.e1 * d1;
    p.z1 = -0.5f * (2.f * LOG2PI_F + __logf(det) + quad);
    return p;
}

template <bool CHILD>
__device__ __forceinline__ float merge_step(const Pre& p, float nmu, float nvar,
                                            float& mu_o, float& var_o)
{
    const float l2   = __fdividef(1.f, nvar);
    const float eta2 = nmu * l2;
    const float den  = (CHILD ? p.dd : p.a) + l2;
    const float keep = CHILD ? p.e0 : p.e1;
    const float es   = (CHILD ? p.e1 : p.e0) + eta2;
    const float rden = __fdividef(1.f, den);
    const float la   = (CHILD ? p.a : p.dd) - p.bo * p.bo * rden;  // > 0 (Schur)
    const float eta  = keep - p.bo * rden * es;
    const float varn = __fdividef(1.f, la);
    const float mun  = varn * eta;
    mu_o = mun;
    var_o = varn;
    // zeta1 + zeta2 - zeta_merge - zeta_new  (logs folded; all args > 0)
    return p.z1 + 0.5f * LOG2PI_F
           - 0.5f * __logf(nvar * den * la)
           - 0.5f * nmu * eta2
           + 0.5f * es  * es  * rden
           + 0.5f * eta * eta * varn;
}

__global__ void scan_k(float* __restrict__ out)
{
    const int tid = blockIdx.x * blockDim.x + threadIdx.x;
    if (tid >= B_ * LL) return;
    const int b  = tid / LL;
    const int ij = tid - b * LL;
    const int j  = ij % L_;

    int m    = b * T_;                // row index (b*T + t), t = 0
    int idx  = m * LL + ij;
    int sidx = m * NS + j;

    float smu  = g_smu[sidx];
    float swv  = g_sw[sidx];
    float svar = __expf(fminf(fmaxf(g_svar[sidx], -1.f), 1.f));

    // t = 0: child-merge with s(t=0), then parent-merge with transition(t=1)
    float mu_c, var_c, mu_p, var_p;
    {
        const Pre p0 = load_pre(m, ij);
        const float sc0 = merge_step<true>(p0, smu, svar, mu_c, var_c);
        const Pre p1 = load_pre(m + 1, ij);
        const float sp0 = merge_step<false>(p1, mu_c, var_c, mu_p, var_p);
        out[idx] = sc0 + sp0 + g_tw[idx] + swv;
    }

    // t = 1 .. T-1 (note: t=1 transition is intentionally used twice, per ref)
    for (int t = 1; t < T_; ++t) {
        ++m;
        idx  += LL;
        sidx += NS;
        smu  = g_smu[sidx];
        swv  = g_sw[sidx];
        svar = __expf(fminf(fmaxf(g_svar[sidx], -1.f), 1.f));

        const float vsum = var_p + svar;
        const float rv   = __fdividef(1.f, vsum);
        const float logv = __logf(vsum);                // vsum > 0
        const float dm   = mu_p - smu;
        const float scale_c = -0.5f * (LOG2PI_F + logv + dm * dm * rv);
        const float mc = (mu_p * svar + smu * var_p) * rv;
        const float vc = vsum - 0.5f * logv;            // > 0 for all vsum > 0

        const Pre p = load_pre(m, ij);
        const float sp = merge_step<false>(p, mc, vc, mu_p, var_p);
        out[idx] = scale_c + sp + g_tw[idx] + swv;
    }
}

// ---------------------------------------------------------------------------
// Launch
// ---------------------------------------------------------------------------
extern "C" void kernel_launch(void* const* d_in, const int* in_sizes, int n_in,
                              void* d_out, int out_size)
{
    const float* x      = (const float*)d_in[0];
    const float* Ws_w   = (const float*)d_in[1];
    const float* bs_w   = (const float*)d_in[2];
    const float* Ws_mu  = (const float*)d_in[3];
    const float* bs_mu  = (const float*)d_in[4];
    const float* Ws_var = (const float*)d_in[5];
    const float* bs_var = (const float*)d_in[6];
    const float* Wt_w   = (const float*)d_in[7];
    const float* bt_w   = (const float*)d_in[8];
    const float* Wt_mu  = (const float*)d_in[9];
    const float* bt_mu  = (const float*)d_in[10];
    const float* Wt_var = (const float*)d_in[11];
    const float* bt_var = (const float*)d_in[12];
    float* out = (float*)d_out;

    float *p_sw, *p_smu, *p_svar, *p_tw, *p_tmu, *p_traw;
    cudaGetSymbolAddress((void**)&p_sw,   g_sw);
    cudaGetSymbolAddress((void**)&p_smu,  g_smu);
    cudaGetSymbolAddress((void**)&p_svar, g_svar);
    cudaGetSymbolAddress((void**)&p_tw,   g_tw);
    cudaGetSymbolAddress((void**)&p_tmu,  g_tmu);
    cudaGetSymbolAddress((void**)&p_traw, g_traw);

    const dim3 blk(256);
    // small heads (N = 51)
    sgemm_k<<<dim3(1, 32), blk>>>(x, Ws_w,   bs_w,   p_sw,   NS);
    sgemm_k<<<dim3(1, 32), blk>>>(x, Ws_mu,  bs_mu,  p_smu,  NS);
    sgemm_k<<<dim3(1, 32), blk>>>(x, Ws_var, bs_var, p_svar, NS);
    // transition heads
    sgemm_k<<<dim3((NTW   + 127) / 128, 32), blk>>>(x, Wt_w,   bt_w,   p_tw,   NTW);
    sgemm_k<<<dim3((NTMU  + 127) / 128, 32), blk>>>(x, Wt_mu,  bt_mu,  p_tmu,  NTMU);
    sgemm_k<<<dim3((NTVAR + 127) / 128, 32), blk>>>(x, Wt_var, bt_var, p_traw, NTVAR);

    // sequential scan over T, parallel over B*L*L chains
    scan_k<<<(B_ * LL + 127) / 128, 128>>>(out);
}

// round 4
// speedup vs baseline: 1.0175x; 1.0175x over previous
#include <cuda_runtime.h>

// Problem constants (fixed shapes from reference)
#define B_   16
#define T_   256
#define D_   512
#define L_   51
#define LL   (L_ * L_)        // 2601
#define M_   (B_ * T_)        // 4096
#define NS   L_               // 51
#define NTW  LL               // 2601
#define NTMU (LL * 2)         // 5202
#define NTVAR (LL * 4)        // 10404
#define LOG2PI_F 1.8378770664093453f

// ---------------------------------------------------------------------------
// Scratch (static __device__ globals; no runtime allocation allowed)
// ---------------------------------------------------------------------------
__device__ float g_sw  [M_ * NS];     // s_w  projections (raw + bias)
__device__ float g_smu [M_ * NS];     // s_mu
__device__ float g_svar[M_ * NS];     // s_var raw (exp(clip) applied in scan)
__device__ float g_tw  [M_ * NTW];    // t_w
__device__ float g_tmu [M_ * NTMU];   // t_mu  (.., 2)
__device__ float g_traw[M_ * NTVAR];  // t_raw (.., 2, 2)

// ---------------------------------------------------------------------------
// fp32 SGEMM: C[M_ x N] = A[M_ x 512] @ W[512 x N] + bias[N]
// BM=128, BN=128, BK=8, 256 threads, 8x8 per-thread microtile.
// M=4096 (divisible by 128), K=512 (divisible by 8); N guarded.
// ---------------------------------------------------------------------------
__global__ __launch_bounds__(256) void sgemm_k(
    const float* __restrict__ A, const float* __restrict__ W,
    const float* __restrict__ bias, float* __restrict__ C, int N)
{
    __shared__ float As[8][128];
    __shared__ float Bs[8][128];

    const int tid = threadIdx.x;
    const int m0 = blockIdx.y * 128;
    const int n0 = blockIdx.x * 128;
    const int ty = tid >> 4;        // 0..15
    const int tx = tid & 15;        // 0..15

    float acc[8][8];
#pragma unroll
    for (int r = 0; r < 8; ++r)
#pragma unroll
        for (int c = 0; c < 8; ++c) acc[r][c] = 0.f;

    const int arow = tid >> 1;        // 0..127
    const int acol = (tid & 1) * 4;   // 0 or 4
    const int brow = tid >> 5;        // 0..7
    const int bcol = (tid & 31) * 4;  // 0..124

    const float* Ap = A + (size_t)(m0 + arow) * D_ + acol;

    for (int kt = 0; kt < D_; kt += 8) {
        // A tile (float4, always aligned: K stride 512, acol multiple of 4)
        float4 av = *reinterpret_cast<const float4*>(Ap + kt);
        As[acol + 0][arow] = av.x;
        As[acol + 1][arow] = av.y;
        As[acol + 2][arow] = av.z;
        As[acol + 3][arow] = av.w;

        // B tile (scalar guarded loads: N may be odd / not multiple of 4)
        const float* Wp = W + (size_t)(kt + brow) * N + n0 + bcol;
#pragma unroll
        for (int u = 0; u < 4; ++u) {
            int gn = n0 + bcol + u;
            Bs[brow][bcol + u] = (gn < N) ? Wp[u] : 0.f;
        }
        __syncthreads();

#pragma unroll
        for (int k = 0; k < 8; ++k) {
            float ar[8], br[8];
#pragma unroll
            for (int r = 0; r < 8; ++r) ar[r] = As[k][ty * 8 + r];
#pragma unroll
            for (int c = 0; c < 8; ++c) br[c] = Bs[k][tx * 8 + c];
#pragma unroll
            for (int r = 0; r < 8; ++r)
#pragma unroll
                for (int c = 0; c < 8; ++c)
                    acc[r][c] = fmaf(ar[r], br[c], acc[r][c]);
        }
        __syncthreads();
    }

#pragma unroll
    for (int r = 0; r < 8; ++r) {
        const int gm = m0 + ty * 8 + r;
#pragma unroll
        for (int c = 0; c < 8; ++c) {
            const int gn = n0 + tx * 8 + c;
            if (gn < N) C[(size_t)gm * N + gn] = acc[r][c] + bias[gn];
        }
    }
}

// ---------------------------------------------------------------------------
// Scan: one thread per (b, i, j) chain; sequential over t.
// Transition prep (exp/tanh/2x2 inverse/zeta1) fused in-place from raw
// projections (avoids a 512MB intermediate round-trip).
// ---------------------------------------------------------------------------
struct Pre { float a, bo, dd, e0, e1, z1; };

__device__ __forceinline__ Pre load_pre(int m, int ij)
{
    const float4 rv = *reinterpret_cast<const float4*>(
        &g_traw[(size_t)m * NTVAR + (size_t)ij * 4]);
    const float2 mv = *reinterpret_cast<const float2*>(
        &g_tmu[(size_t)m * NTMU + (size_t)ij * 2]);

    const float c0 = fminf(fmaxf(rv.x, -1.f), 1.f);   // t_raw[...,0,0]
    const float c1 = fminf(fmaxf(rv.w, -1.f), 1.f);   // t_raw[...,1,1]
    const float d0 = __expf(c0);
    const float d1 = __expf(c1);
    const float s  = rv.y + rv.z;                     // r01 + r10
    // tanh(0.5*s) = 1 - 2/(exp(s)+1)   (saturates correctly at +/-1)
    const float th  = 1.f - 2.f * __fdividef(1.f, __expf(s) + 1.f);
    // sqrt(d0*d1) = exp(0.5*(c0+c1))
    const float off = 0.9f * th * __expf(0.5f * (c0 + c1));

    const float det  = d0 * d1 - off * off;           // >= 0.19*d0*d1 > 0
    const float rdet = __fdividef(1.f, det);
    Pre p;
    p.a  = d1 * rdet;
    p.bo = -off * rdet;
    p.dd = d0 * rdet;
    p.e0 = p.a  * mv.x + p.bo * mv.y;
    p.e1 = p.bo * mv.x + p.dd * mv.y;
    const float quad = p.e0 * p.e0 * d0 + 2.f * p.e0 * p.e1 * off + p.e1 * p.e1 * d1;
    p.z1 = -0.5f * (2.f * LOG2PI_F + __logf(det) + quad);
    return p;
}

template <bool CHILD>
__device__ __forceinline__ float merge_step(const Pre& p, float nmu, float nvar,
                                            float& mu_o, float& var_o)
{
    const float l2   = __fdividef(1.f, nvar);
    const float eta2 = nmu * l2;
    const float den  = (CHILD ? p.dd : p.a) + l2;
    const float keep = CHILD ? p.e0 : p.e1;
    const float es   = (CHILD ? p.e1 : p.e0) + eta2;
    const float rden = __fdividef(1.f, den);
    const float la   = (CHILD ? p.a : p.dd) - p.bo * p.bo * rden;  // > 0 (Schur)
    const float eta  = keep - p.bo * rden * es;
    const float varn = __fdividef(1.f, la);
    const float mun  = varn * eta;
    mu_o = mun;
    var_o = varn;
    // zeta1 + zeta2 - zeta_merge - zeta_new  (logs folded; all args > 0)
    return p.z1 + 0.5f * LOG2PI_F
           - 0.5f * __logf(nvar * den * la)
           - 0.5f * nmu * eta2
           + 0.5f * es  * es  * rden
           + 0.5f * eta * eta * varn;
}

__global__ void scan_k(float* __restrict__ out)
{
    const int tid = blockIdx.x * blockDim.x + threadIdx.x;
    if (tid >= B_ * LL) return;
    const int b  = tid / LL;
    const int ij = tid - b * LL;
    const int j  = ij % L_;

    int m    = b * T_;                // row index (b*T + t), t = 0
    int idx  = m * LL + ij;
    int sidx = m * NS + j;

    float smu  = g_smu[sidx];
    float swv  = g_sw[sidx];
    float svar = __expf(fminf(fmaxf(g_svar[sidx], -1.f), 1.f));

    // t = 0: child-merge with s(t=0), then parent-merge with transition(t=1)
    float mu_c, var_c, mu_p, var_p;
    {
        const Pre p0 = load_pre(m, ij);
        const float sc0 = merge_step<true>(p0, smu, svar, mu_c, var_c);
        const Pre p1 = load_pre(m + 1, ij);
        const float sp0 = merge_step<false>(p1, mu_c, var_c, mu_p, var_p);
        out[idx] = sc0 + sp0 + g_tw[idx] + swv;
    }

    // t = 1 .. T-1 (note: t=1 transition is intentionally used twice, per ref)
    for (int t = 1; t < T_; ++t) {
        ++m;
        idx  += LL;
        sidx += NS;
        smu  = g_smu[sidx];
        swv  = g_sw[sidx];
        svar = __expf(fminf(fmaxf(g_svar[sidx], -1.f), 1.f));

        const float vsum = var_p + svar;
        const float rv   = __fdividef(1.f, vsum);
        const float logv = __logf(vsum);                // vsum > 0
        const float dm   = mu_p - smu;
        const float scale_c = -0.5f * (LOG2PI_F + logv + dm * dm * rv);
        const float mc = (mu_p * svar + smu * var_p) * rv;
        const float vc = vsum - 0.5f * logv;            // > 0 for all vsum > 0

        const Pre p = load_pre(m, ij);
        const float sp = merge_step<false>(p, mc, vc, mu_p, var_p);
        out[idx] = scale_c + sp + g_tw[idx] + swv;
    }
}

// ---------------------------------------------------------------------------
// Launch
// ---------------------------------------------------------------------------
extern "C" void kernel_launch(void* const* d_in, const int* in_sizes, int n_in,
                              void* d_out, int out_size)
{
    const float* x      = (const float*)d_in[0];
    const float* Ws_w   = (const float*)d_in[1];
    const float* bs_w   = (const float*)d_in[2];
    const float* Ws_mu  = (const float*)d_in[3];
    const float* bs_mu  = (const float*)d_in[4];
    const float* Ws_var = (const float*)d_in[5];
    const float* bs_var = (const float*)d_in[6];
    const float* Wt_w   = (const float*)d_in[7];
    const float* bt_w   = (const float*)d_in[8];
    const float* Wt_mu  = (const float*)d_in[9];
    const float* bt_mu  = (const float*)d_in[10];
    const float* Wt_var = (const float*)d_in[11];
    const float* bt_var = (const float*)d_in[12];
    float* out = (float*)d_out;

    float *p_sw, *p_smu, *p_svar, *p_tw, *p_tmu, *p_traw;
    cudaGetSymbolAddress((void**)&p_sw,   g_sw);
    cudaGetSymbolAddress((void**)&p_smu,  g_smu);
    cudaGetSymbolAddress((void**)&p_svar, g_svar);
    cudaGetSymbolAddress((void**)&p_tw,   g_tw);
    cudaGetSymbolAddress((void**)&p_tmu,  g_tmu);
    cudaGetSymbolAddress((void**)&p_traw, g_traw);

    const dim3 blk(256);
    // small heads (N = 51)
    sgemm_k<<<dim3(1, 32), blk>>>(x, Ws_w,   bs_w,   p_sw,   NS);
    sgemm_k<<<dim3(1, 32), blk>>>(x, Ws_mu,  bs_mu,  p_smu,  NS);
    sgemm_k<<<dim3(1, 32), blk>>>(x, Ws_var, bs_var, p_svar, NS);
    // transition heads
    sgemm_k<<<dim3((NTW   + 127) / 128, 32), blk>>>(x, Wt_w,   bt_w,   p_tw,   NTW);
    sgemm_k<<<dim3((NTMU  + 127) / 128, 32), blk>>>(x, Wt_mu,  bt_mu,  p_tmu,  NTMU);
    sgemm_k<<<dim3((NTVAR + 127) / 128, 32), blk>>>(x, Wt_var, bt_var, p_traw, NTVAR);

    // sequential scan over T, parallel over B*L*L chains
    scan_k<<<(B_ * LL + 127) / 128, 128>>>(out);
}

// round 8
// speedup vs baseline: 3.2995x; 3.2427x over previous
#include <cuda_runtime.h>
#include <cuda_bf16.h>
#include <cstdint>

// ---------------------------------------------------------------------------
// Problem constants
// ---------------------------------------------------------------------------
#define B_    16
#define T_    256
#define D_    512
#define L_    51
#define LL    (L_ * L_)          // 2601
#define M_    (B_ * T_)          // 4096
#define NTOT  18360              // 51*3 + 2601 + 5202 + 10404
#define OFF_SW   0
#define OFF_SMU  51
#define OFF_SVAR 102
#define OFF_TW   153
#define OFF_TMU  2754
#define OFF_TVAR 7956
#define LOG2PI_F 1.8378770664093453f

// GEMM tiling
#define BM 128
#define BN 128
#define BK 64
#define NK (D_ / BK)                 // 8 k-stages
#define TILE_B (128 * 128)           // one tile: 128 rows x 64 bf16 (128B) = 16KB
#define STAGE_B (4 * TILE_B)         // Ahi, Alo, Bhi, Blo = 64KB
#define SMEM_GEMM (2 * STAGE_B)      // double buffered = 128KB
#define NTILE_N ((NTOT + BN - 1) / BN)   // 144

// ---------------------------------------------------------------------------
// Static device scratch
// ---------------------------------------------------------------------------
__device__ __nv_bfloat16 g_xhi[M_ * D_];
__device__ __nv_bfloat16 g_xlo[M_ * D_];
__device__ __nv_bfloat16 g_whi[NTOT * D_];   // transposed: [n][k]
__device__ __nv_bfloat16 g_wlo[NTOT * D_];
__device__ float g_bias[NTOT];
__device__ float g_C[(size_t)M_ * NTOT];     // all projections, row stride NTOT

// ---------------------------------------------------------------------------
// PTX helpers (all plain sm_80+ features; no 'a'-suffix instructions)
// ---------------------------------------------------------------------------
__device__ __forceinline__ uint32_t smem_u32(const void* p) {
    uint32_t a;
    asm("{ .reg .u64 t; cvta.to.shared.u64 t, %1; cvt.u32.u64 %0, t; }"
        : "=r"(a) : "l"(p));
    return a;
}
__device__ __forceinline__ void cpa16(uint32_t saddr, const void* g) {
    asm volatile("cp.async.cg.shared.global [%0], [%1], 16;"
                 :: "r"(saddr), "l"(g) : "memory");
}
#define CP_COMMIT() asm volatile("cp.async.commit_group;" ::: "memory")
#define CP_WAIT(n)  asm volatile("cp.async.wait_group %0;" :: "n"(n) : "memory")

__device__ __forceinline__ void ldm4(uint32_t& r0, uint32_t& r1,
                                     uint32_t& r2, uint32_t& r3, uint32_t a) {
    asm volatile("ldmatrix.sync.aligned.m8n8.x4.shared.b16 {%0,%1,%2,%3}, [%4];"
                 : "=r"(r0), "=r"(r1), "=r"(r2), "=r"(r3) : "r"(a));
}
__device__ __forceinline__ void mma16816(float* c, const uint32_t* a,
                                         const uint32_t* b) {
    asm volatile(
        "mma.sync.aligned.m16n8k16.row.col.f32.bf16.bf16.f32 "
        "{%0,%1,%2,%3}, {%4,%5,%6,%7}, {%8,%9}, {%0,%1,%2,%3};"
        : "+f"(c[0]), "+f"(c[1]), "+f"(c[2]), "+f"(c[3])
        : "r"(a[0]), "r"(a[1]), "r"(a[2]), "r"(a[3]), "r"(b[0]), "r"(b[1]));
}

// ---------------------------------------------------------------------------
// Conversion kernels
// ---------------------------------------------------------------------------
__global__ void conv_x_k(const float* __restrict__ x,
                         __nv_bfloat16* __restrict__ xhi,
                         __nv_bfloat16* __restrict__ xlo) {
    int i = blockIdx.x * blockDim.x + threadIdx.x;
    if (i >= M_ * D_) return;
    float v = x[i];
    __nv_bfloat16 h = __float2bfloat16(v);
    xhi[i] = h;
    xlo[i] = __float2bfloat16(v - __bfloat162float(h));
}

// Tiled transpose + split: W[512 x N] -> Wt_hi/lo[(off+n) x 512]
__global__ void conv_w_k(const float* __restrict__ W, int N, int off,
                         __nv_bfloat16* __restrict__ whi,
                         __nv_bfloat16* __restrict__ wlo) {
    __shared__ float t[32][33];
    const int n0 = blockIdx.x * 32, k0 = blockIdx.y * 32;
    const int tx = threadIdx.x, ty = threadIdx.y;  // (32, 8)
#pragma unroll
    for (int r = 0; r < 4; ++r) {
        int k = k0 + ty + 8 * r, n = n0 + tx;
        t[ty + 8 * r][tx] = (n < N) ? W[(size_t)k * N + n] : 0.f;
    }
    __syncthreads();
#pragma unroll
    for (int r = 0; r < 4; ++r) {
        int n = n0 + ty + 8 * r, k = k0 + tx;
        if (n < N) {
            float v = t[tx][ty + 8 * r];
            __nv_bfloat16 h = __float2bfloat16(v);
            size_t o = (size_t)(off + n) * D_ + k;
            whi[o] = h;
            wlo[o] = __float2bfloat16(v - __bfloat162float(h));
        }
    }
}

__global__ void bias_k(const float* b0, const float* b1, const float* b2,
                       const float* b3, const float* b4, const float* b5,
                       float* __restrict__ dst) {
    int i = blockIdx.x * blockDim.x + threadIdx.x;
    if (i >= NTOT) return;
    float v;
    if      (i < 51)   v = b0[i];
    else if (i < 102)  v = b1[i - 51];
    else if (i < 153)  v = b2[i - 102];
    else if (i < 2754) v = b3[i - 153];
    else if (i < 7956) v = b4[i - 2754];
    else               v = b5[i - 7956];
    dst[i] = v;
}

// ---------------------------------------------------------------------------
// Split-bf16 tensor-core GEMM via mma.sync (HMMA):
// C = x @ W + bias  with  Ahi*Bhi + Ahi*Blo + Alo*Bhi   (fp32 accum)
// 128x128 CTA tile, BK=64, 8 warps (64x32 each), cp.async double buffer,
// SW128-swizzled SMEM + conflict-free ldmatrix.
// ---------------------------------------------------------------------------
__device__ __forceinline__ void load_stage(
    const __nv_bfloat16* __restrict__ xhi, const __nv_bfloat16* __restrict__ xlo,
    const __nv_bfloat16* __restrict__ whi, const __nv_bfloat16* __restrict__ wlo,
    uint32_t stage, int m0, int n0, int kc, int tid)
{
#pragma unroll
    for (int it = 0; it < 4; ++it) {
        const int idx = tid + it * 256;       // 0..1023
        const int row = idx >> 3;             // 0..127
        const int seg = idx & 7;              // 16B segment
        const uint32_t sw = row * 128 + (((seg ^ (row & 7))) << 4);
        const size_t ga = (size_t)(m0 + row) * D_ + kc + seg * 8;
        const int brow = (n0 + row < NTOT) ? (n0 + row) : (NTOT - 1);  // clamp (unused cols)
        const size_t gb = (size_t)brow * D_ + kc + seg * 8;
        cpa16(stage + 0 * TILE_B + sw, xhi + ga);
        cpa16(stage + 1 * TILE_B + sw, xlo + ga);
        cpa16(stage + 2 * TILE_B + sw, whi + gb);
        cpa16(stage + 3 * TILE_B + sw, wlo + gb);
    }
}

__global__ __launch_bounds__(256, 1)
void mma_gemm_k(const __nv_bfloat16* __restrict__ xhi,
                const __nv_bfloat16* __restrict__ xlo,
                const __nv_bfloat16* __restrict__ whi,
                const __nv_bfloat16* __restrict__ wlo,
                const float* __restrict__ bias,
                float* __restrict__ C)
{
    extern __shared__ char smem[];
    const uint32_t sb = smem_u32(smem);
    const int tid = threadIdx.x;
    const int wid = tid >> 5;
    const int lane = tid & 31;
    const int m0 = blockIdx.y * BM;
    const int n0 = blockIdx.x * BN;
    const int wm = wid >> 2;        // 0..1  (64-row slab)
    const int wn = wid & 3;         // 0..3  (32-col slab)

    // ldmatrix per-lane mapping (g = lane/8, ri = lane%8)
    const int g  = lane >> 3;
    const int ri = lane & 7;
    const int a_row_in   = ((g & 1) << 3) + ri;   // row within 16-row m-tile
    const int a_seg_half = g >> 1;                // k half (0/1)
    const int b_row_in   = ((g >> 1) << 3) + ri;  // row within 16-row n-pair
    const int b_seg_half = g & 1;

    // Per-lane swizzle-folded base offsets (addr = base ^ (seg<<4))
    uint32_t aBase[4], bBase[2];
#pragma unroll
    for (int mt = 0; mt < 4; ++mt) {
        const int r = wm * 64 + mt * 16 + a_row_in;
        aBase[mt] = r * 128 + ((r & 7) << 4);
    }
#pragma unroll
    for (int pt = 0; pt < 2; ++pt) {
        const int r = wn * 32 + pt * 16 + b_row_in;
        bBase[pt] = r * 128 + ((r & 7) << 4);
    }

    float acc[4][4][4];
#pragma unroll
    for (int mt = 0; mt < 4; ++mt)
#pragma unroll
        for (int nt = 0; nt < 4; ++nt)
#pragma unroll
            for (int q = 0; q < 4; ++q) acc[mt][nt][q] = 0.f;

    // prologue: stage 0
    load_stage(xhi, xlo, whi, wlo, sb, m0, n0, 0, tid);
    CP_COMMIT();

    for (int c = 0; c < NK; ++c) {
        if (c + 1 < NK) {
            load_stage(xhi, xlo, whi, wlo, sb + ((c + 1) & 1) * STAGE_B,
                       m0, n0, (c + 1) * BK, tid);
            CP_COMMIT();
            CP_WAIT(1);
        } else {
            CP_WAIT(0);
        }
        __syncthreads();

        const uint32_t st = sb + (c & 1) * STAGE_B;
#pragma unroll
        for (int kq = 0; kq < 4; ++kq) {
            uint32_t ahi[4][4], alo[4][4], bhi[4][2], blo[4][2];
            const uint32_t aSegX = (uint32_t)((2 * kq + a_seg_half) << 4);
            const uint32_t bSegX = (uint32_t)((2 * kq + b_seg_half) << 4);
#pragma unroll
            for (int mt = 0; mt < 4; ++mt) {
                const uint32_t ax = aBase[mt] ^ aSegX;
                ldm4(ahi[mt][0], ahi[mt][1], ahi[mt][2], ahi[mt][3],
                     st + 0 * TILE_B + ax);
                ldm4(alo[mt][0], alo[mt][1], alo[mt][2], alo[mt][3],
                     st + 1 * TILE_B + ax);
            }
#pragma unroll
            for (int pt = 0; pt < 2; ++pt) {
                const uint32_t bx = bBase[pt] ^ bSegX;
                // x4 covers two n-tiles: regs {b0,b1} tile 2pt, {b2,b3} tile 2pt+1
                ldm4(bhi[2 * pt][0], bhi[2 * pt][1], bhi[2 * pt + 1][0],
                     bhi[2 * pt + 1][1], st + 2 * TILE_B + bx);
                ldm4(blo[2 * pt][0], blo[2 * pt][1], blo[2 * pt + 1][0],
                     blo[2 * pt + 1][1], st + 3 * TILE_B + bx);
            }
#pragma unroll
            for (int mt = 0; mt < 4; ++mt)
#pragma unroll
                for (int nt = 0; nt < 4; ++nt) {
                    mma16816(acc[mt][nt], ahi[mt], bhi[nt]);
                    mma16816(acc[mt][nt], ahi[mt], blo[nt]);
                    mma16816(acc[mt][nt], alo[mt], bhi[nt]);
                }
        }
        __syncthreads();
    }

    // epilogue: c0,c1 at (row l/4, col 2*(l%4)), c2,c3 at row+8
    const int er = lane >> 2;
    const int ec = (lane & 3) * 2;
#pragma unroll
    for (int mt = 0; mt < 4; ++mt) {
        const int gr = m0 + wm * 64 + mt * 16 + er;
#pragma unroll
        for (int nt = 0; nt < 4; ++nt) {
            const int gc = n0 + wn * 32 + nt * 8 + ec;
            if (gc < NTOT) {   // NTOT even & gc even => gc+1 also valid
                const float b0 = bias[gc], b1 = bias[gc + 1];
                float2 v0 = make_float2(acc[mt][nt][0] + b0, acc[mt][nt][1] + b1);
                float2 v1 = make_float2(acc[mt][nt][2] + b0, acc[mt][nt][3] + b1);
                *reinterpret_cast<float2*>(C + (size_t)gr * NTOT + gc) = v0;
                *reinterpret_cast<float2*>(C + (size_t)(gr + 8) * NTOT + gc) = v1;
            }
        }
    }
}

// ---------------------------------------------------------------------------
// Scan (unchanged math; reads from the fused C buffer)
// ---------------------------------------------------------------------------
struct Pre { float a, bo, dd, e0, e1, z1; };

__device__ __forceinline__ Pre load_pre(const float* __restrict__ C, int m, int ij) {
    const float4 rv = *reinterpret_cast<const float4*>(
        C + (size_t)m * NTOT + OFF_TVAR + (size_t)ij * 4);
    const float2 mv = *reinterpret_cast<const float2*>(
        C + (size_t)m * NTOT + OFF_TMU + (size_t)ij * 2);

    const float c0 = fminf(fmaxf(rv.x, -1.f), 1.f);
    const float c1 = fminf(fmaxf(rv.w, -1.f), 1.f);
    const float d0 = __expf(c0);
    const float d1 = __expf(c1);
    const float s  = rv.y + rv.z;
    const float th  = 1.f - 2.f * __fdividef(1.f, __expf(s) + 1.f);
    const float off = 0.9f * th * __expf(0.5f * (c0 + c1));

    const float det  = d0 * d1 - off * off;
    const float rdet = __fdividef(1.f, det);
    Pre p;
    p.a  = d1 * rdet;
    p.bo = -off * rdet;
    p.dd = d0 * rdet;
    p.e0 = p.a  * mv.x + p.bo * mv.y;
    p.e1 = p.bo * mv.x + p.dd * mv.y;
    const float quad = p.e0 * p.e0 * d0 + 2.f * p.e0 * p.e1 * off + p.e1 * p.e1 * d1;
    p.z1 = -0.5f * (2.f * LOG2PI_F + __logf(det) + quad);
    return p;
}

template <bool CHILD>
__device__ __forceinline__ float merge_step(const Pre& p, float nmu, float nvar,
                                            float& mu_o, float& var_o) {
    const float l2   = __fdividef(1.f, nvar);
    const float eta2 = nmu * l2;
    const float den  = (CHILD ? p.dd : p.a) + l2;
    const float keep = CHILD ? p.e0 : p.e1;
    const float es   = (CHILD ? p.e1 : p.e0) + eta2;
    const float rden = __fdividef(1.f, den);
    const float la   = (CHILD ? p.a : p.dd) - p.bo * p.bo * rden;
    const float eta  = keep - p.bo * rden * es;
    const float varn = __fdividef(1.f, la);
    mu_o = varn * eta;
    var_o = varn;
    return p.z1 + 0.5f * LOG2PI_F
           - 0.5f * __logf(nvar * den * la)
           - 0.5f * nmu * eta2
           + 0.5f * es  * es  * rden
           + 0.5f * eta * eta * varn;
}

__global__ void scan_k(const float* __restrict__ C, float* __restrict__ out) {
    const int tid = blockIdx.x * blockDim.x + threadIdx.x;
    if (tid >= B_ * LL) return;
    const int b  = tid / LL;
    const int ij = tid - b * LL;
    const int j  = ij % L_;

    int m   = b * T_;
    size_t idx = (size_t)m * LL + ij;

    const float* Crow = C + (size_t)m * NTOT;
    float smu  = Crow[OFF_SMU + j];
    float swv  = Crow[OFF_SW + j];
    float svar = __expf(fminf(fmaxf(Crow[OFF_SVAR + j], -1.f), 1.f));

    float mu_c, var_c, mu_p, var_p;
    {
        const Pre p0 = load_pre(C, m, ij);
        const float sc0 = merge_step<true>(p0, smu, svar, mu_c, var_c);
        const Pre p1 = load_pre(C, m + 1, ij);
        const float sp0 = merge_step<false>(p1, mu_c, var_c, mu_p, var_p);
        out[idx] = sc0 + sp0 + Crow[OFF_TW + ij] + swv;
    }

    for (int t = 1; t < T_; ++t) {
        ++m;
        idx += LL;
        const float* Cr = C + (size_t)m * NTOT;
        smu  = Cr[OFF_SMU + j];
        swv  = Cr[OFF_SW + j];
        svar = __expf(fminf(fmaxf(Cr[OFF_SVAR + j], -1.f), 1.f));

        const float vsum = var_p + svar;
        const float rv   = __fdividef(1.f, vsum);
        const float logv = __logf(vsum);
        const float dm   = mu_p - smu;
        const float scale_c = -0.5f * (LOG2PI_F + logv + dm * dm * rv);
        const float mc = (mu_p * svar + smu * var_p) * rv;
        const float vc = vsum - 0.5f * logv;

        const Pre p = load_pre(C, m, ij);
        const float sp = merge_step<false>(p, mc, vc, mu_p, var_p);
        out[idx] = scale_c + sp + Cr[OFF_TW + ij] + swv;
    }
}

// ---------------------------------------------------------------------------
// Launch
// ---------------------------------------------------------------------------
extern "C" void kernel_launch(void* const* d_in, const int* in_sizes, int n_in,
                              void* d_out, int out_size)
{
    const float* x      = (const float*)d_in[0];
    const float* Ws_w   = (const float*)d_in[1];
    const float* bs_w   = (const float*)d_in[2];
    const float* Ws_mu  = (const float*)d_in[3];
    const float* bs_mu  = (const float*)d_in[4];
    const float* Ws_var = (const float*)d_in[5];
    const float* bs_var = (const float*)d_in[6];
    const float* Wt_w   = (const float*)d_in[7];
    const float* bt_w   = (const float*)d_in[8];
    const float* Wt_mu  = (const float*)d_in[9];
    const float* bt_mu  = (const float*)d_in[10];
    const float* Wt_var = (const float*)d_in[11];
    const float* bt_var = (const float*)d_in[12];
    float* out = (float*)d_out;

    __nv_bfloat16 *p_xhi, *p_xlo, *p_whi, *p_wlo;
    float *p_bias, *p_C;
    cudaGetSymbolAddress((void**)&p_xhi,  g_xhi);
    cudaGetSymbolAddress((void**)&p_xlo,  g_xlo);
    cudaGetSymbolAddress((void**)&p_whi,  g_whi);
    cudaGetSymbolAddress((void**)&p_wlo,  g_wlo);
    cudaGetSymbolAddress((void**)&p_bias, g_bias);
    cudaGetSymbolAddress((void**)&p_C,    g_C);

    cudaFuncSetAttribute(mma_gemm_k, cudaFuncAttributeMaxDynamicSharedMemorySize,
                         SMEM_GEMM);

    // 1) fp32 -> bf16 hi/lo conversions (x as-is, weights transposed+concat)
    conv_x_k<<<(M_ * D_ + 255) / 256, 256>>>(x, p_xhi, p_xlo);
    dim3 tb(32, 8);
    conv_w_k<<<dim3((51    + 31) / 32, 16), tb>>>(Ws_w,   51,    OFF_SW,   p_whi, p_wlo);
    conv_w_k<<<dim3((51    + 31) / 32, 16), tb>>>(Ws_mu,  51,    OFF_SMU,  p_whi, p_wlo);
    conv_w_k<<<dim3((51    + 31) / 32, 16), tb>>>(Ws_var, 51,    OFF_SVAR, p_whi, p_wlo);
    conv_w_k<<<dim3((2601  + 31) / 32, 16), tb>>>(Wt_w,   2601,  OFF_TW,   p_whi, p_wlo);
    conv_w_k<<<dim3((5202  + 31) / 32, 16), tb>>>(Wt_mu,  5202,  OFF_TMU,  p_whi, p_wlo);
    conv_w_k<<<dim3((10404 + 31) / 32, 16), tb>>>(Wt_var, 10404, OFF_TVAR, p_whi, p_wlo);
    bias_k<<<(NTOT + 255) / 256, 256>>>(bs_w, bs_mu, bs_var, bt_w, bt_mu, bt_var, p_bias);

    // 2) fused split-bf16 HMMA GEMM over all heads
    mma_gemm_k<<<dim3(NTILE_N, M_ / BM), 256, SMEM_GEMM>>>(
        p_xhi, p_xlo, p_whi, p_wlo, p_bias, p_C);

    // 3) sequential scan over T, parallel over B*L*L chains
    scan_k<<<(B_ * LL + 127) / 128, 128>>>(p_C, out);
}

// round 11
// speedup vs baseline: 3.5366x; 1.0719x over previous
#include <cuda_runtime.h>
#include <cuda_bf16.h>
#include <cstdint>

// ---------------------------------------------------------------------------
// Problem constants
// ---------------------------------------------------------------------------
#define B_    16
#define T_    256
#define D_    512
#define L_    51
#define LL    (L_ * L_)          // 2601
#define M_    (B_ * T_)          // 4096
#define NTOT  18360              // 51*3 + 2601 + 5202 + 10404
#define OFF_SW   0
#define OFF_SMU  51
#define OFF_SVAR 102
#define OFF_TW   153
#define OFF_TMU  2754
#define OFF_TVAR 7956
#define LOG2PI_F 1.8378770664093453f

// GEMM tiling
#define BM 128
#define BN 128
#define BK 64
#define NK (D_ / BK)                 // 8 k-chunks
#define TILE_B (128 * 128)           // one tile: 128 rows x 64 bf16 (128B) = 16KB
#define STAGE_B (4 * TILE_B)         // Ahi, Alo, Bhi, Blo = 64KB
#define NSTAGE 3
#define SMEM_GEMM (NSTAGE * STAGE_B) // 192KB
#define NTILE_N ((NTOT + BN - 1) / BN)   // 144

// ---------------------------------------------------------------------------
// Static device scratch
// ---------------------------------------------------------------------------
__device__ __nv_bfloat16 g_xhi[M_ * D_];
__device__ __nv_bfloat16 g_xlo[M_ * D_];
__device__ __nv_bfloat16 g_whi[NTOT * D_];   // transposed: [n][k]
__device__ __nv_bfloat16 g_wlo[NTOT * D_];
__device__ float g_bias[NTOT];
__device__ float g_C[(size_t)M_ * NTOT];     // all projections, row stride NTOT

// ---------------------------------------------------------------------------
// PTX helpers (plain sm_80+ features only)
// ---------------------------------------------------------------------------
__device__ __forceinline__ uint32_t smem_u32(const void* p) {
    uint32_t a;
    asm("{ .reg .u64 t; cvta.to.shared.u64 t, %1; cvt.u32.u64 %0, t; }"
        : "=r"(a) : "l"(p));
    return a;
}
__device__ __forceinline__ void cpa16(uint32_t saddr, const void* g) {
    asm volatile("cp.async.cg.shared.global [%0], [%1], 16;"
                 :: "r"(saddr), "l"(g) : "memory");
}
#define CP_COMMIT() asm volatile("cp.async.commit_group;" ::: "memory")
#define CP_WAIT(n)  asm volatile("cp.async.wait_group %0;" :: "n"(n) : "memory")

__device__ __forceinline__ void ldm4(uint32_t& r0, uint32_t& r1,
                                     uint32_t& r2, uint32_t& r3, uint32_t a) {
    asm volatile("ldmatrix.sync.aligned.m8n8.x4.shared.b16 {%0,%1,%2,%3}, [%4];"
                 : "=r"(r0), "=r"(r1), "=r"(r2), "=r"(r3) : "r"(a));
}
__device__ __forceinline__ void mma16816(float* c, const uint32_t* a,
                                         const uint32_t* b) {
    asm volatile(
        "mma.sync.aligned.m16n8k16.row.col.f32.bf16.bf16.f32 "
        "{%0,%1,%2,%3}, {%4,%5,%6,%7}, {%8,%9}, {%0,%1,%2,%3};"
        : "+f"(c[0]), "+f"(c[1]), "+f"(c[2]), "+f"(c[3])
        : "r"(a[0]), "r"(a[1]), "r"(a[2]), "r"(a[3]), "r"(b[0]), "r"(b[1]));
}

// ---------------------------------------------------------------------------
// Conversion kernels
// ---------------------------------------------------------------------------
__global__ void conv_x_k(const float* __restrict__ x,
                         __nv_bfloat16* __restrict__ xhi,
                         __nv_bfloat16* __restrict__ xlo) {
    int i = blockIdx.x * blockDim.x + threadIdx.x;
    if (i >= M_ * D_) return;
    float v = x[i];
    __nv_bfloat16 h = __float2bfloat16(v);
    xhi[i] = h;
    xlo[i] = __float2bfloat16(v - __bfloat162float(h));
}

// One fused tiled transpose + split for all six weight matrices.
// blockIdx.z selects the source; W[512 x N] -> Wt_hi/lo[(off+n) x 512]
__global__ void conv_w_all_k(const float* __restrict__ W0, const float* __restrict__ W1,
                             const float* __restrict__ W2, const float* __restrict__ W3,
                             const float* __restrict__ W4, const float* __restrict__ W5,
                             __nv_bfloat16* __restrict__ whi,
                             __nv_bfloat16* __restrict__ wlo) {
    const int src = blockIdx.z;
    const float* W;
    int N, off;
    switch (src) {
        case 0:  W = W0; N = 51;    off = OFF_SW;   break;
        case 1:  W = W1; N = 51;    off = OFF_SMU;  break;
        case 2:  W = W2; N = 51;    off = OFF_SVAR; break;
        case 3:  W = W3; N = 2601;  off = OFF_TW;   break;
        case 4:  W = W4; N = 5202;  off = OFF_TMU;  break;
        default: W = W5; N = 10404; off = OFF_TVAR; break;
    }
    const int n0 = blockIdx.x * 32, k0 = blockIdx.y * 32;
    if (n0 >= N) return;
    __shared__ float t[32][33];
    const int tx = threadIdx.x, ty = threadIdx.y;  // (32, 8)
#pragma unroll
    for (int r = 0; r < 4; ++r) {
        int k = k0 + ty + 8 * r, n = n0 + tx;
        t[ty + 8 * r][tx] = (n < N) ? W[(size_t)k * N + n] : 0.f;
    }
    __syncthreads();
#pragma unroll
    for (int r = 0; r < 4; ++r) {
        int n = n0 + ty + 8 * r, k = k0 + tx;
        if (n < N) {
            float v = t[tx][ty + 8 * r];
            __nv_bfloat16 h = __float2bfloat16(v);
            size_t o = (size_t)(off + n) * D_ + k;
            whi[o] = h;
            wlo[o] = __float2bfloat16(v - __bfloat162float(h));
        }
    }
}

__global__ void bias_k(const float* b0, const float* b1, const float* b2,
                       const float* b3, const float* b4, const float* b5,
                       float* __restrict__ dst) {
    int i = blockIdx.x * blockDim.x + threadIdx.x;
    if (i >= NTOT) return;
    float v;
    if      (i < 51)   v = b0[i];
    else if (i < 102)  v = b1[i - 51];
    else if (i < 153)  v = b2[i - 102];
    else if (i < 2754) v = b3[i - 153];
    else if (i < 7956) v = b4[i - 2754];
    else               v = b5[i - 7956];
    dst[i] = v;
}

// ---------------------------------------------------------------------------
// Split-bf16 HMMA GEMM: C = x @ W + bias  (Ahi*Bhi + Ahi*Blo + Alo*Bhi)
// 128x128 CTA tile, BK=64, 8 warps (64x32 each), 3-stage cp.async pipeline,
// SW128-swizzled SMEM, SMEM-staged coalesced epilogue.
// ---------------------------------------------------------------------------
__device__ __forceinline__ void load_stage(
    const __nv_bfloat16* __restrict__ xhi, const __nv_bfloat16* __restrict__ xlo,
    const __nv_bfloat16* __restrict__ whi, const __nv_bfloat16* __restrict__ wlo,
    uint32_t stage, int m0, int n0, int kc, int tid)
{
#pragma unroll
    for (int it = 0; it < 4; ++it) {
        const int idx = tid + it * 256;       // 0..1023
        const int row = idx >> 3;             // 0..127
        const int seg = idx & 7;              // 16B segment
        const uint32_t sw = row * 128 + (((seg ^ (row & 7))) << 4);
        const size_t ga = (size_t)(m0 + row) * D_ + kc + seg * 8;
        const int brow = (n0 + row < NTOT) ? (n0 + row) : (NTOT - 1);  // clamp
        const size_t gb = (size_t)brow * D_ + kc + seg * 8;
        cpa16(stage + 0 * TILE_B + sw, xhi + ga);
        cpa16(stage + 1 * TILE_B + sw, xlo + ga);
        cpa16(stage + 2 * TILE_B + sw, whi + gb);
        cpa16(stage + 3 * TILE_B + sw, wlo + gb);
    }
}

__global__ __launch_bounds__(256, 1)
void mma_gemm_k(const __nv_bfloat16* __restrict__ xhi,
                const __nv_bfloat16* __restrict__ xlo,
                const __nv_bfloat16* __restrict__ whi,
                const __nv_bfloat16* __restrict__ wlo,
                const float* __restrict__ bias,
                float* __restrict__ C)
{
    extern __shared__ char smem[];
    const uint32_t sb = smem_u32(smem);
    const int tid = threadIdx.x;
    const int wid = tid >> 5;
    const int lane = tid & 31;
    const int m0 = blockIdx.y * BM;
    const int n0 = blockIdx.x * BN;
    const int wm = wid >> 2;        // 0..1  (64-row slab)
    const int wn = wid & 3;         // 0..3  (32-col slab)

    // ldmatrix per-lane mapping (g = lane/8, ri = lane%8)
    const int g  = lane >> 3;
    const int ri = lane & 7;
    const int a_row_in   = ((g & 1) << 3) + ri;
    const int a_seg_half = g >> 1;
    const int b_row_in   = ((g >> 1) << 3) + ri;
    const int b_seg_half = g & 1;

    uint32_t aBase[4], bBase[2];
#pragma unroll
    for (int mt = 0; mt < 4; ++mt) {
        const int r = wm * 64 + mt * 16 + a_row_in;
        aBase[mt] = r * 128 + ((r & 7) << 4);
    }
#pragma unroll
    for (int pt = 0; pt < 2; ++pt) {
        const int r = wn * 32 + pt * 16 + b_row_in;
        bBase[pt] = r * 128 + ((r & 7) << 4);
    }

    float acc[4][4][4];
#pragma unroll
    for (int mt = 0; mt < 4; ++mt)
#pragma unroll
        for (int nt = 0; nt < 4; ++nt)
#pragma unroll
            for (int q = 0; q < 4; ++q) acc[mt][nt][q] = 0.f;

    // prologue: stages 0,1
    load_stage(xhi, xlo, whi, wlo, sb + 0 * STAGE_B, m0, n0, 0 * BK, tid);
    CP_COMMIT();
    load_stage(xhi, xlo, whi, wlo, sb + 1 * STAGE_B, m0, n0, 1 * BK, tid);
    CP_COMMIT();

    int sidx = 0;                       // stage index = c % 3
    for (int c = 0; c < NK; ++c) {
        if (c + 2 < NK) {
            int ns = sidx + 2; if (ns >= NSTAGE) ns -= NSTAGE;
            load_stage(xhi, xlo, whi, wlo, sb + ns * STAGE_B,
                       m0, n0, (c + 2) * BK, tid);
            CP_COMMIT();
            CP_WAIT(2);
        } else if (c + 2 == NK) {
            CP_WAIT(1);
        } else {
            CP_WAIT(0);
        }
        __syncthreads();

        const uint32_t st = sb + sidx * STAGE_B;
#pragma unroll
        for (int kq = 0; kq < 4; ++kq) {
            uint32_t ahi[4][4], alo[4][4], bhi[4][2], blo[4][2];
            const uint32_t aSegX = (uint32_t)((2 * kq + a_seg_half) << 4);
            const uint32_t bSegX = (uint32_t)((2 * kq + b_seg_half) << 4);
#pragma unroll
            for (int mt = 0; mt < 4; ++mt) {
                const uint32_t ax = aBase[mt] ^ aSegX;
                ldm4(ahi[mt][0], ahi[mt][1], ahi[mt][2], ahi[mt][3],
                     st + 0 * TILE_B + ax);
                ldm4(alo[mt][0], alo[mt][1], alo[mt][2], alo[mt][3],
                     st + 1 * TILE_B + ax);
            }
#pragma unroll
            for (int pt = 0; pt < 2; ++pt) {
                const uint32_t bx = bBase[pt] ^ bSegX;
                ldm4(bhi[2 * pt][0], bhi[2 * pt][1], bhi[2 * pt + 1][0],
                     bhi[2 * pt + 1][1], st + 2 * TILE_B + bx);
                ldm4(blo[2 * pt][0], blo[2 * pt][1], blo[2 * pt + 1][0],
                     blo[2 * pt + 1][1], st + 3 * TILE_B + bx);
            }
#pragma unroll
            for (int mt = 0; mt < 4; ++mt)
#pragma unroll
                for (int nt = 0; nt < 4; ++nt) {
                    mma16816(acc[mt][nt], ahi[mt], bhi[nt]);
                    mma16816(acc[mt][nt], ahi[mt], blo[nt]);
                    mma16816(acc[mt][nt], alo[mt], bhi[nt]);
                }
        }
        __syncthreads();
        if (++sidx == NSTAGE) sidx = 0;
    }

    // ---- SMEM-staged epilogue: coalesced 128B-row stores with fused bias ----
    float* stage_f = reinterpret_cast<float*>(smem);   // 64KB of stage 0
    const int er = lane >> 2;
    const int ec = (lane & 3) * 2;
#pragma unroll
    for (int mt = 0; mt < 4; ++mt) {
        const int r0 = wm * 64 + mt * 16 + er;
#pragma unroll
        for (int nt = 0; nt < 4; ++nt) {
            const int cc = wn * 32 + nt * 8 + ec;
            *reinterpret_cast<float2*>(stage_f + r0 * 128 + cc) =
                make_float2(acc[mt][nt][0], acc[mt][nt][1]);
            *reinterpret_cast<float2*>(stage_f + (r0 + 8) * 128 + cc) =
                make_float2(acc[mt][nt][2], acc[mt][nt][3]);
        }
    }
    __syncthreads();
#pragma unroll
    for (int it = 0; it < 16; ++it) {
        const int idx = tid + it * 256;   // 0..4095  (128 rows x 32 float4)
        const int row = idx >> 5;
        const int seg = idx & 31;
        const int gc = n0 + seg * 4;
        if (gc < NTOT) {                  // NTOT % 4 == 0 -> whole float4 valid
            const float4 v  = *reinterpret_cast<const float4*>(stage_f + row * 128 + seg * 4);
            const float4 bv = *reinterpret_cast<const float4*>(bias + gc);
            float4 o = make_float4(v.x + bv.x, v.y + bv.y, v.z + bv.z, v.w + bv.w);
            *reinterpret_cast<float4*>(C + (size_t)(m0 + row) * NTOT + gc) = o;
        }
    }
}

// ---------------------------------------------------------------------------
// Scan: one thread per (b,i,j) chain; software-pipelined loads.
// ---------------------------------------------------------------------------
struct Pre { float a, bo, dd, e0, e1, z1; };
struct RawT { float4 rv; float2 mv; };

__device__ __forceinline__ RawT load_raw(const float* __restrict__ C, int m, int ij) {
    RawT r;
    r.rv = *reinterpret_cast<const float4*>(
        C + (size_t)m * NTOT + OFF_TVAR + (size_t)ij * 4);
    r.mv = *reinterpret_cast<const float2*>(
        C + (size_t)m * NTOT + OFF_TMU + (size_t)ij * 2);
    return r;
}

__device__ __forceinline__ Pre make_pre(const RawT& r) {
    const float c0 = fminf(fmaxf(r.rv.x, -1.f), 1.f);
    const float c1 = fminf(fmaxf(r.rv.w, -1.f), 1.f);
    const float d0 = __expf(c0);
    const float d1 = __expf(c1);
    const float s  = r.rv.y + r.rv.z;
    const float th  = 1.f - 2.f * __fdividef(1.f, __expf(s) + 1.f);
    const float off = 0.9f * th * __expf(0.5f * (c0 + c1));

    const float det  = d0 * d1 - off * off;
    const float rdet = __fdividef(1.f, det);
    Pre p;
    p.a  = d1 * rdet;
    p.bo = -off * rdet;
    p.dd = d0 * rdet;
    p.e0 = p.a  * r.mv.x + p.bo * r.mv.y;
    p.e1 = p.bo * r.mv.x + p.dd * r.mv.y;
    const float quad = p.e0 * p.e0 * d0 + 2.f * p.e0 * p.e1 * off + p.e1 * p.e1 * d1;
    p.z1 = -0.5f * (2.f * LOG2PI_F + __logf(det) + quad);
    return p;
}

template <bool CHILD>
__device__ __forceinline__ float merge_step(const Pre& p, float nmu, float nvar,
                                            float& mu_o, float& var_o) {
    const float l2   = __fdividef(1.f, nvar);
    const float eta2 = nmu * l2;
    const float den  = (CHILD ? p.dd : p.a) + l2;
    const float keep = CHILD ? p.e0 : p.e1;
    const float es   = (CHILD ? p.e1 : p.e0) + eta2;
    const float rden = __fdividef(1.f, den);
    const float la   = (CHILD ? p.a : p.dd) - p.bo * p.bo * rden;
    const float eta  = keep - p.bo * rden * es;
    const float varn = __fdividef(1.f, la);
    mu_o = varn * eta;
    var_o = varn;
    return p.z1 + 0.5f * LOG2PI_F
           - 0.5f * __logf(nvar * den * la)
           - 0.5f * nmu * eta2
           + 0.5f * es  * es  * rden
           + 0.5f * eta * eta * varn;
}

__global__ void scan_k(const float* __restrict__ C, float* __restrict__ out) {
    const int tid = blockIdx.x * blockDim.x + threadIdx.x;
    if (tid >= B_ * LL) return;
    const int b  = tid / LL;
    const int ij = tid - b * LL;
    const int j  = ij % L_;

    const int mbase = b * T_;
    size_t idx = (size_t)mbase * LL + ij;

    // ---- t = 0 ----
    float mu_c, var_c, mu_p, var_p;
    {
        const float* Cr = C + (size_t)mbase * NTOT;
        const float smu = Cr[OFF_SMU + j];
        const float swv = Cr[OFF_SW + j];
        const float svar = __expf(fminf(fmaxf(Cr[OFF_SVAR + j], -1.f), 1.f));
        const Pre p0 = make_pre(load_raw(C, mbase, ij));
        const float sc0 = merge_step<true>(p0, smu, svar, mu_c, var_c);
        const RawT r1 = load_raw(C, mbase + 1, ij);   // row mbase+1: reused at t=1
        const Pre p1 = make_pre(r1);
        const float sp0 = merge_step<false>(p1, mu_c, var_c, mu_p, var_p);
        out[idx] = sc0 + sp0 + Cr[OFF_TW + ij] + swv;
    }

    // ---- pipelined t = 1 .. T-1 ----
    // current-state regs for step t; prefetch step t+1 before computing t.
    const float* Cr1 = C + (size_t)(mbase + 1) * NTOT;
    RawT  raw_c = load_raw(C, mbase + 1, ij);         // same row as p1 (L1/L2 hit)
    float smu_c = Cr1[OFF_SMU + j];
    float sw_c  = Cr1[OFF_SW + j];
    float svr_c = Cr1[OFF_SVAR + j];
    float tw_c  = Cr1[OFF_TW + ij];

    for (int t = 1; t < T_; ++t) {
        // prefetch next step (clamped so loads stay unconditional)
        const int mn = (t + 1 < T_) ? (mbase + t + 1) : (mbase + T_ - 1);
        const float* Cn = C + (size_t)mn * NTOT;
        const RawT  raw_n = load_raw(C, mn, ij);
        const float smu_n = Cn[OFF_SMU + j];
        const float sw_n  = Cn[OFF_SW + j];
        const float svr_n = Cn[OFF_SVAR + j];
        const float tw_n  = Cn[OFF_TW + ij];

        // compute step t from current regs
        const float svar = __expf(fminf(fmaxf(svr_c, -1.f), 1.f));
        const float vsum = var_p + svar;
        const float rv   = __fdividef(1.f, vsum);
        const float logv = __logf(vsum);
        const float dm   = mu_p - smu_c;
        const float scale_c = -0.5f * (LOG2PI_F + logv + dm * dm * rv);
        const float mc = (mu_p * svar + smu_c * var_p) * rv;
        const float vc = vsum - 0.5f * logv;

        const Pre p = make_pre(raw_c);
        const float sp = merge_step<false>(p, mc, vc, mu_p, var_p);
        idx += LL;
        out[idx] = scale_c + sp + tw_c + sw_c;

        raw_c = raw_n; smu_c = smu_n; sw_c = sw_n; svr_c = svr_n; tw_c = tw_n;
    }
}

// ---------------------------------------------------------------------------
// Launch
// ---------------------------------------------------------------------------
extern "C" void kernel_launch(void* const* d_in, const int* in_sizes, int n_in,
                              void* d_out, int out_size)
{
    const float* x      = (const float*)d_in[0];
    const float* Ws_w   = (const float*)d_in[1];
    const float* bs_w   = (const float*)d_in[2];
    const float* Ws_mu  = (const float*)d_in[3];
    const float* bs_mu  = (const float*)d_in[4];
    const float* Ws_var = (const float*)d_in[5];
    const float* bs_var = (const float*)d_in[6];
    const float* Wt_w   = (const float*)d_in[7];
    const float* bt_w   = (const float*)d_in[8];
    const float* Wt_mu  = (const float*)d_in[9];
    const float* bt_mu  = (const float*)d_in[10];
    const float* Wt_var = (const float*)d_in[11];
    const float* bt_var = (const float*)d_in[12];
    float* out = (float*)d_out;

    __nv_bfloat16 *p_xhi, *p_xlo, *p_whi, *p_wlo;
    float *p_bias, *p_C;
    cudaGetSymbolAddress((void**)&p_xhi,  g_xhi);
    cudaGetSymbolAddress((void**)&p_xlo,  g_xlo);
    cudaGetSymbolAddress((void**)&p_whi,  g_whi);
    cudaGetSymbolAddress((void**)&p_wlo,  g_wlo);
    cudaGetSymbolAddress((void**)&p_bias, g_bias);
    cudaGetSymbolAddress((void**)&p_C,    g_C);

    cudaFuncSetAttribute(mma_gemm_k, cudaFuncAttributeMaxDynamicSharedMemorySize,
                         SMEM_GEMM);

    // 1) fp32 -> bf16 hi/lo conversions
    conv_x_k<<<(M_ * D_ + 255) / 256, 256>>>(x, p_xhi, p_xlo);
    conv_w_all_k<<<dim3((10404 + 31) / 32, 16, 6), dim3(32, 8)>>>(
        Ws_w, Ws_mu, Ws_var, Wt_w, Wt_mu, Wt_var, p_whi, p_wlo);
    bias_k<<<(NTOT + 255) / 256, 256>>>(bs_w, bs_mu, bs_var, bt_w, bt_mu, bt_var, p_bias);

    // 2) fused split-bf16 HMMA GEMM over all heads
    mma_gemm_k<<<dim3(NTILE_N, M_ / BM), 256, SMEM_GEMM>>>(
        p_xhi, p_xlo, p_whi, p_wlo, p_bias, p_C);

    // 3) sequential scan over T, parallel over B*L*L chains
    scan_k<<<(B_ * LL + 255) / 256, 256>>>(p_C, out);
}

// round 12
// speedup vs baseline: 3.5491x; 1.0035x over previous
#include <cuda_runtime.h>
#include <cuda_bf16.h>
#include <cstdint>

// ---------------------------------------------------------------------------
// Problem constants
// ---------------------------------------------------------------------------
#define B_    16
#define T_    256
#define D_    512
#define L_    51
#define LL    (L_ * L_)          // 2601
#define M_    (B_ * T_)          // 4096
#define NTOT  18360              // 51*3 + 2601 + 5202 + 10404
#define OFF_SW   0
#define OFF_SMU  51
#define OFF_SVAR 102
#define OFF_TW   153
#define OFF_TMU  2754
#define OFF_TVAR 7956
#define LOG2PI_F 1.8378770664093453f

// GEMM tiling: CTA 128x256, 8 warps of 64x64, BK=64, 2-stage pipeline
#define BM 128
#define BN 256
#define BK 64
#define NK (D_ / BK)                 // 8 k-chunks
#define A_TILE_B (128 * 128)         // 128 rows x 128B = 16KB
#define B_TILE_B (256 * 128)         // 256 rows x 128B = 32KB
#define ST_AHI 0
#define ST_ALO (A_TILE_B)
#define ST_BHI (2 * A_TILE_B)
#define ST_BLO (2 * A_TILE_B + B_TILE_B)
#define STAGE_B (2 * A_TILE_B + 2 * B_TILE_B)   // 96KB
#define SMEM_GEMM (2 * STAGE_B)                 // 192KB
#define NTILE_N ((NTOT + BN - 1) / BN)          // 72

// ---------------------------------------------------------------------------
// Static device scratch
// ---------------------------------------------------------------------------
__device__ __nv_bfloat16 g_xhi[M_ * D_];
__device__ __nv_bfloat16 g_xlo[M_ * D_];
__device__ __nv_bfloat16 g_whi[NTOT * D_];   // transposed: [n][k]
__device__ __nv_bfloat16 g_wlo[NTOT * D_];
__device__ float g_bias[NTOT];
__device__ float g_C[(size_t)M_ * NTOT];     // all projections, row stride NTOT

// ---------------------------------------------------------------------------
// PTX helpers (plain sm_80+ features only)
// ---------------------------------------------------------------------------
__device__ __forceinline__ uint32_t smem_u32(const void* p) {
    uint32_t a;
    asm("{ .reg .u64 t; cvta.to.shared.u64 t, %1; cvt.u32.u64 %0, t; }"
        : "=r"(a) : "l"(p));
    return a;
}
__device__ __forceinline__ void cpa16(uint32_t saddr, const void* g) {
    asm volatile("cp.async.cg.shared.global [%0], [%1], 16;"
                 :: "r"(saddr), "l"(g) : "memory");
}
#define CP_COMMIT() asm volatile("cp.async.commit_group;" ::: "memory")
#define CP_WAIT(n)  asm volatile("cp.async.wait_group %0;" :: "n"(n) : "memory")

__device__ __forceinline__ void ldm4(uint32_t& r0, uint32_t& r1,
                                     uint32_t& r2, uint32_t& r3, uint32_t a) {
    asm volatile("ldmatrix.sync.aligned.m8n8.x4.shared.b16 {%0,%1,%2,%3}, [%4];"
                 : "=r"(r0), "=r"(r1), "=r"(r2), "=r"(r3) : "r"(a));
}
__device__ __forceinline__ void mma16816(float* c, const uint32_t* a,
                                         const uint32_t* b) {
    asm volatile(
        "mma.sync.aligned.m16n8k16.row.col.f32.bf16.bf16.f32 "
        "{%0,%1,%2,%3}, {%4,%5,%6,%7}, {%8,%9}, {%0,%1,%2,%3};"
        : "+f"(c[0]), "+f"(c[1]), "+f"(c[2]), "+f"(c[3])
        : "r"(a[0]), "r"(a[1]), "r"(a[2]), "r"(a[3]), "r"(b[0]), "r"(b[1]));
}

// ---------------------------------------------------------------------------
// Conversion kernels
// ---------------------------------------------------------------------------
__global__ void conv_x_k(const float* __restrict__ x,
                         __nv_bfloat16* __restrict__ xhi,
                         __nv_bfloat16* __restrict__ xlo) {
    int i = blockIdx.x * blockDim.x + threadIdx.x;
    if (i >= M_ * D_) return;
    float v = x[i];
    __nv_bfloat16 h = __float2bfloat16(v);
    xhi[i] = h;
    xlo[i] = __float2bfloat16(v - __bfloat162float(h));
}

// One fused tiled transpose + split for all six weight matrices.
__global__ void conv_w_all_k(const float* __restrict__ W0, const float* __restrict__ W1,
                             const float* __restrict__ W2, const float* __restrict__ W3,
                             const float* __restrict__ W4, const float* __restrict__ W5,
                             __nv_bfloat16* __restrict__ whi,
                             __nv_bfloat16* __restrict__ wlo) {
    const int src = blockIdx.z;
    const float* W;
    int N, off;
    switch (src) {
        case 0:  W = W0; N = 51;    off = OFF_SW;   break;
        case 1:  W = W1; N = 51;    off = OFF_SMU;  break;
        case 2:  W = W2; N = 51;    off = OFF_SVAR; break;
        case 3:  W = W3; N = 2601;  off = OFF_TW;   break;
        case 4:  W = W4; N = 5202;  off = OFF_TMU;  break;
        default: W = W5; N = 10404; off = OFF_TVAR; break;
    }
    const int n0 = blockIdx.x * 32, k0 = blockIdx.y * 32;
    if (n0 >= N) return;
    __shared__ float t[32][33];
    const int tx = threadIdx.x, ty = threadIdx.y;  // (32, 8)
#pragma unroll
    for (int r = 0; r < 4; ++r) {
        int k = k0 + ty + 8 * r, n = n0 + tx;
        t[ty + 8 * r][tx] = (n < N) ? W[(size_t)k * N + n] : 0.f;
    }
    __syncthreads();
#pragma unroll
    for (int r = 0; r < 4; ++r) {
        int n = n0 + ty + 8 * r, k = k0 + tx;
        if (n < N) {
            float v = t[tx][ty + 8 * r];
            __nv_bfloat16 h = __float2bfloat16(v);
            size_t o = (size_t)(off + n) * D_ + k;
            whi[o] = h;
            wlo[o] = __float2bfloat16(v - __bfloat162float(h));
        }
    }
}

__global__ void bias_k(const float* b0, const float* b1, const float* b2,
                       const float* b3, const float* b4, const float* b5,
                       float* __restrict__ dst) {
    int i = blockIdx.x * blockDim.x + threadIdx.x;
    if (i >= NTOT) return;
    float v;
    if      (i < 51)   v = b0[i];
    else if (i < 102)  v = b1[i - 51];
    else if (i < 153)  v = b2[i - 102];
    else if (i < 2754) v = b3[i - 153];
    else if (i < 7956) v = b4[i - 2754];
    else               v = b5[i - 7956];
    dst[i] = v;
}

// ---------------------------------------------------------------------------
// Split-bf16 HMMA GEMM: C = x @ W + bias  (Ahi*Bhi + Ahi*Blo + Alo*Bhi)
// CTA 128x256, 8 warps of 64x64, BK=64, 2-stage cp.async pipeline.
// ---------------------------------------------------------------------------
__device__ __forceinline__ void load_stage(
    const __nv_bfloat16* __restrict__ xhi, const __nv_bfloat16* __restrict__ xlo,
    const __nv_bfloat16* __restrict__ whi, const __nv_bfloat16* __restrict__ wlo,
    uint32_t stage, int m0, int n0, int kc, int tid)
{
    // A tiles: 128 rows x 8 segs = 1024 chunks each (hi, lo)
#pragma unroll
    for (int it = 0; it < 4; ++it) {
        const int idx = tid + it * 256;       // 0..1023
        const int row = idx >> 3;
        const int seg = idx & 7;
        const uint32_t sw = row * 128 + (((seg ^ (row & 7))) << 4);
        const size_t ga = (size_t)(m0 + row) * D_ + kc + seg * 8;
        cpa16(stage + ST_AHI + sw, xhi + ga);
        cpa16(stage + ST_ALO + sw, xlo + ga);
    }
    // B tiles: 256 rows x 8 segs = 2048 chunks each (hi, lo)
#pragma unroll
    for (int it = 0; it < 8; ++it) {
        const int idx = tid + it * 256;       // 0..2047
        const int row = idx >> 3;
        const int seg = idx & 7;
        const uint32_t sw = row * 128 + (((seg ^ (row & 7))) << 4);
        const int brow = (n0 + row < NTOT) ? (n0 + row) : (NTOT - 1);  // clamp
        const size_t gb = (size_t)brow * D_ + kc + seg * 8;
        cpa16(stage + ST_BHI + sw, whi + gb);
        cpa16(stage + ST_BLO + sw, wlo + gb);
    }
}

__global__ __launch_bounds__(256, 1)
void mma_gemm_k(const __nv_bfloat16* __restrict__ xhi,
                const __nv_bfloat16* __restrict__ xlo,
                const __nv_bfloat16* __restrict__ whi,
                const __nv_bfloat16* __restrict__ wlo,
                const float* __restrict__ bias,
                float* __restrict__ C)
{
    extern __shared__ char smem[];
    const uint32_t sb = smem_u32(smem);
    const int tid = threadIdx.x;
    const int wid = tid >> 5;
    const int lane = tid & 31;
    const int m0 = blockIdx.y * BM;
    const int n0 = blockIdx.x * BN;
    const int wm = wid >> 2;        // 0..1  (64-row slab)
    const int wn = wid & 3;         // 0..3  (64-col slab)

    // ldmatrix per-lane mapping (g = lane/8, ri = lane%8)
    const int g  = lane >> 3;
    const int ri = lane & 7;
    const int a_row_in   = ((g & 1) << 3) + ri;
    const int a_seg_half = g >> 1;
    const int b_row_in   = ((g >> 1) << 3) + ri;
    const int b_seg_half = g & 1;

    uint32_t aBase[4], bBase[4];
#pragma unroll
    for (int mt = 0; mt < 4; ++mt) {
        const int r = wm * 64 + mt * 16 + a_row_in;
        aBase[mt] = r * 128 + ((r & 7) << 4);
    }
#pragma unroll
    for (int pt = 0; pt < 4; ++pt) {
        const int r = wn * 64 + pt * 16 + b_row_in;
        bBase[pt] = r * 128 + ((r & 7) << 4);
    }

    float acc[4][8][4];
#pragma unroll
    for (int mt = 0; mt < 4; ++mt)
#pragma unroll
        for (int nt = 0; nt < 8; ++nt)
#pragma unroll
            for (int q = 0; q < 4; ++q) acc[mt][nt][q] = 0.f;

    // prologue: stage 0
    load_stage(xhi, xlo, whi, wlo, sb, m0, n0, 0, tid);
    CP_COMMIT();

    for (int c = 0; c < NK; ++c) {
        if (c + 1 < NK) {
            load_stage(xhi, xlo, whi, wlo, sb + ((c + 1) & 1) * STAGE_B,
                       m0, n0, (c + 1) * BK, tid);
            CP_COMMIT();
            CP_WAIT(1);
        } else {
            CP_WAIT(0);
        }
        __syncthreads();

        const uint32_t st = sb + (c & 1) * STAGE_B;
#pragma unroll
        for (int kq = 0; kq < 4; ++kq) {
            const uint32_t aSegX = (uint32_t)((2 * kq + a_seg_half) << 4);
            const uint32_t bSegX = (uint32_t)((2 * kq + b_seg_half) << 4);
            uint32_t ahi[4][4], alo[4][4];
#pragma unroll
            for (int mt = 0; mt < 4; ++mt) {
                const uint32_t ax = aBase[mt] ^ aSegX;
                ldm4(ahi[mt][0], ahi[mt][1], ahi[mt][2], ahi[mt][3],
                     st + ST_AHI + ax);
                ldm4(alo[mt][0], alo[mt][1], alo[mt][2], alo[mt][3],
                     st + ST_ALO + ax);
            }
#pragma unroll
            for (int pt = 0; pt < 4; ++pt) {
                const uint32_t bx = bBase[pt] ^ bSegX;
                uint32_t bhi[4], blo[4];   // two n-tiles: {0,1} and {2,3}
                ldm4(bhi[0], bhi[1], bhi[2], bhi[3], st + ST_BHI + bx);
                ldm4(blo[0], blo[1], blo[2], blo[3], st + ST_BLO + bx);
#pragma unroll
                for (int sub = 0; sub < 2; ++sub) {
                    const int nt = 2 * pt + sub;
#pragma unroll
                    for (int mt = 0; mt < 4; ++mt) {
                        mma16816(acc[mt][nt], ahi[mt], bhi + 2 * sub);
                        mma16816(acc[mt][nt], ahi[mt], blo + 2 * sub);
                        mma16816(acc[mt][nt], alo[mt], bhi + 2 * sub);
                    }
                }
            }
        }
        __syncthreads();
    }

    // ---- SMEM-staged epilogue: coalesced stores with fused bias ----
    float* stage_f = reinterpret_cast<float*>(smem);   // 128KB <= 192KB
    const int er = lane >> 2;
    const int ec = (lane & 3) * 2;
#pragma unroll
    for (int mt = 0; mt < 4; ++mt) {
        const int r0 = wm * 64 + mt * 16 + er;
#pragma unroll
        for (int nt = 0; nt < 8; ++nt) {
            const int cc = wn * 64 + nt * 8 + ec;
            *reinterpret_cast<float2*>(stage_f + r0 * 256 + cc) =
                make_float2(acc[mt][nt][0], acc[mt][nt][1]);
            *reinterpret_cast<float2*>(stage_f + (r0 + 8) * 256 + cc) =
                make_float2(acc[mt][nt][2], acc[mt][nt][3]);
        }
    }
    __syncthreads();
#pragma unroll
    for (int it = 0; it < 32; ++it) {
        const int idx = tid + it * 256;   // 0..8191  (128 rows x 64 float4)
        const int row = idx >> 6;
        const int seg = idx & 63;
        const int gc = n0 + seg * 4;
        if (gc < NTOT) {                  // NTOT % 4 == 0 -> whole float4 valid
            const float4 v  = *reinterpret_cast<const float4*>(stage_f + row * 256 + seg * 4);
            const float4 bv = *reinterpret_cast<const float4*>(bias + gc);
            float4 o = make_float4(v.x + bv.x, v.y + bv.y, v.z + bv.z, v.w + bv.w);
            *reinterpret_cast<float4*>(C + (size_t)(m0 + row) * NTOT + gc) = o;
        }
    }
}

// ---------------------------------------------------------------------------
// Scan: one thread per (b,i,j) chain; 2-deep software pipeline.
// ---------------------------------------------------------------------------
struct Pre { float a, bo, dd, e0, e1, z1; };
struct Step { float4 rv; float2 mv; float smu, sw, svar, tw; };

__device__ __forceinline__ Step load_step(const float* __restrict__ C, int m,
                                          int ij, int j) {
    const float* Cr = C + (size_t)m * NTOT;
    Step s;
    s.rv = *reinterpret_cast<const float4*>(Cr + OFF_TVAR + (size_t)ij * 4);
    s.mv = *reinterpret_cast<const float2*>(Cr + OFF_TMU + (size_t)ij * 2);
    s.smu = Cr[OFF_SMU + j];
    s.sw  = Cr[OFF_SW + j];
    s.svar = Cr[OFF_SVAR + j];
    s.tw  = Cr[OFF_TW + ij];
    return s;
}

__device__ __forceinline__ Pre make_pre(const float4 rv, const float2 mv) {
    const float c0 = fminf(fmaxf(rv.x, -1.f), 1.f);
    const float c1 = fminf(fmaxf(rv.w, -1.f), 1.f);
    const float d0 = __expf(c0);
    const float d1 = __expf(c1);
    const float s  = rv.y + rv.z;
    const float th  = 1.f - 2.f * __fdividef(1.f, __expf(s) + 1.f);
    const float off = 0.9f * th * __expf(0.5f * (c0 + c1));

    const float det  = d0 * d1 - off * off;
    const float rdet = __fdividef(1.f, det);
    Pre p;
    p.a  = d1 * rdet;
    p.bo = -off * rdet;
    p.dd = d0 * rdet;
    p.e0 = p.a  * mv.x + p.bo * mv.y;
    p.e1 = p.bo * mv.x + p.dd * mv.y;
    const float quad = p.e0 * p.e0 * d0 + 2.f * p.e0 * p.e1 * off + p.e1 * p.e1 * d1;
    p.z1 = -0.5f * (2.f * LOG2PI_F + __logf(det) + quad);
    return p;
}

template <bool CHILD>
__device__ __forceinline__ float merge_step(const Pre& p, float nmu, float nvar,
                                            float& mu_o, float& var_o) {
    const float l2   = __fdividef(1.f, nvar);
    const float eta2 = nmu * l2;
    const float den  = (CHILD ? p.dd : p.a) + l2;
    const float keep = CHILD ? p.e0 : p.e1;
    const float es   = (CHILD ? p.e1 : p.e0) + eta2;
    const float rden = __fdividef(1.f, den);
    const float la   = (CHILD ? p.a : p.dd) - p.bo * p.bo * rden;
    const float eta  = keep - p.bo * rden * es;
    const float varn = __fdividef(1.f, la);
    mu_o = varn * eta;
    var_o = varn;
    return p.z1 + 0.5f * LOG2PI_F
           - 0.5f * __logf(nvar * den * la)
           - 0.5f * nmu * eta2
           + 0.5f * es  * es  * rden
           + 0.5f * eta * eta * varn;
}

__global__ void scan_k(const float* __restrict__ C, float* __restrict__ out) {
    const int tid = blockIdx.x * blockDim.x + threadIdx.x;
    if (tid >= B_ * LL) return;
    const int b  = tid / LL;
    const int ij = tid - b * LL;
    const int j  = ij % L_;

    const int mbase = b * T_;
    size_t idx = (size_t)mbase * LL + ij;

    // ---- t = 0 ----
    float mu_c, var_c, mu_p, var_p;
    {
        const float* Cr = C + (size_t)mbase * NTOT;
        const float smu = Cr[OFF_SMU + j];
        const float swv = Cr[OFF_SW + j];
        const float svar = __expf(fminf(fmaxf(Cr[OFF_SVAR + j], -1.f), 1.f));
        const float4 rv0 = *reinterpret_cast<const float4*>(Cr + OFF_TVAR + (size_t)ij * 4);
        const float2 mv0 = *reinterpret_cast<const float2*>(Cr + OFF_TMU + (size_t)ij * 2);
        const Pre p0 = make_pre(rv0, mv0);
        const float sc0 = merge_step<true>(p0, smu, svar, mu_c, var_c);
        const Step s1 = load_step(C, mbase + 1, ij, j);
        const Pre p1 = make_pre(s1.rv, s1.mv);
        const float sp0 = merge_step<false>(p1, mu_c, var_c, mu_p, var_p);
        out[idx] = sc0 + sp0 + Cr[OFF_TW + ij] + swv;
    }

    // ---- pipelined t = 1 .. T-1, 2-deep prefetch ----
    Step sa = load_step(C, mbase + 1, ij, j);                        // t=1 (L2 hit)
    Step sb = load_step(C, mbase + (2 < T_ ? 2 : T_ - 1), ij, j);    // t=2

    for (int t = 1; t < T_; ++t) {
        // prefetch step t+2 (clamped)
        const int mn = (t + 2 < T_) ? (mbase + t + 2) : (mbase + T_ - 1);
        const Step sc = load_step(C, mn, ij, j);

        // compute step t from sa
        const float svar = __expf(fminf(fmaxf(sa.svar, -1.f), 1.f));
        const float vsum = var_p + svar;
        const float rv   = __fdividef(1.f, vsum);
        const float logv = __logf(vsum);
        const float dm   = mu_p - sa.smu;
        const float scale_c = -0.5f * (LOG2PI_F + logv + dm * dm * rv);
        const float mc = (mu_p * svar + sa.smu * var_p) * rv;
        const float vc = vsum - 0.5f * logv;

        const Pre p = make_pre(sa.rv, sa.mv);
        const float sp = merge_step<false>(p, mc, vc, mu_p, var_p);
        idx += LL;
        out[idx] = scale_c + sp + sa.tw + sa.sw;

        sa = sb; sb = sc;
    }
}

// ---------------------------------------------------------------------------
// Launch
// ---------------------------------------------------------------------------
extern "C" void kernel_launch(void* const* d_in, const int* in_sizes, int n_in,
                              void* d_out, int out_size)
{
    const float* x      = (const float*)d_in[0];
    const float* Ws_w   = (const float*)d_in[1];
    const float* bs_w   = (const float*)d_in[2];
    const float* Ws_mu  = (const float*)d_in[3];
    const float* bs_mu  = (const float*)d_in[4];
    const float* Ws_var = (const float*)d_in[5];
    const float* bs_var = (const float*)d_in[6];
    const float* Wt_w   = (const float*)d_in[7];
    const float* bt_w   = (const float*)d_in[8];
    const float* Wt_mu  = (const float*)d_in[9];
    const float* bt_mu  = (const float*)d_in[10];
    const float* Wt_var = (const float*)d_in[11];
    const float* bt_var = (const float*)d_in[12];
    float* out = (float*)d_out;

    __nv_bfloat16 *p_xhi, *p_xlo, *p_whi, *p_wlo;
    float *p_bias, *p_C;
    cudaGetSymbolAddress((void**)&p_xhi,  g_xhi);
    cudaGetSymbolAddress((void**)&p_xlo,  g_xlo);
    cudaGetSymbolAddress((void**)&p_whi,  g_whi);
    cudaGetSymbolAddress((void**)&p_wlo,  g_wlo);
    cudaGetSymbolAddress((void**)&p_bias, g_bias);
    cudaGetSymbolAddress((void**)&p_C,    g_C);

    cudaFuncSetAttribute(mma_gemm_k, cudaFuncAttributeMaxDynamicSharedMemorySize,
                         SMEM_GEMM);

    // 1) fp32 -> bf16 hi/lo conversions
    conv_x_k<<<(M_ * D_ + 255) / 256, 256>>>(x, p_xhi, p_xlo);
    conv_w_all_k<<<dim3((10404 + 31) / 32, 16, 6), dim3(32, 8)>>>(
        Ws_w, Ws_mu, Ws_var, Wt_w, Wt_mu, Wt_var, p_whi, p_wlo);
    bias_k<<<(NTOT + 255) / 256, 256>>>(bs_w, bs_mu, bs_var, bt_w, bt_mu, bt_var, p_bias);

    // 2) fused split-bf16 HMMA GEMM over all heads
    mma_gemm_k<<<dim3(NTILE_N, M_ / BM), 256, SMEM_GEMM>>>(
        p_xhi, p_xlo, p_whi, p_wlo, p_bias, p_C);

    // 3) sequential scan over T, parallel over B*L*L chains
    scan_k<<<(B_ * LL + 255) / 256, 256>>>(p_C, out);
}